// round 2
// baseline (speedup 1.0000x reference)
#include <cuda_runtime.h>
#include <cstdint>

#define C_IN   128
#define C_OUT  256
#define KK     9
#define HW     64
#define NBATCH 16
#define KDIM   (C_IN * KK)   // 1152
#define CH     8             // channel chunk per smem stage

// Fused weight scratch, transposed to [ck][oc] for coalesced conv-side loads.
__device__ float g_weffT[KDIM * C_OUT];

// ---------------------------------------------------------------------------
// Kernel 1: W_eff[o][ck] = W[o][ck] + 2.0 * sum_r B[o][r] * A[r][ck]
// stored transposed: g_weffT[ck*256 + o]
// ---------------------------------------------------------------------------
__global__ void fuse_weights_kernel(const float* __restrict__ W,
                                    const float* __restrict__ lora_A,
                                    const float* __restrict__ lora_B) {
    int idx = blockIdx.x * blockDim.x + threadIdx.x;
    if (idx >= C_OUT * KDIM) return;
    int o  = idx & (C_OUT - 1);   // fastest -> coalesced writes
    int ck = idx >> 8;            // 0..1151
    float s = 0.f;
#pragma unroll
    for (int r = 0; r < 8; ++r)
        s += lora_B[o * 8 + r] * lora_A[r * KDIM + ck];
    g_weffT[ck * C_OUT + o] = W[o * KDIM + ck] + 2.0f * s;
}

// ---------------------------------------------------------------------------
// f32x2 packed-FMA helpers (FFMA2 — 2x fp32 throughput on sm_103a)
// ---------------------------------------------------------------------------
typedef unsigned long long u64;

__device__ __forceinline__ u64 pack2(float a, float b) {
    u64 r;
    asm("mov.b64 %0, {%1, %2};"
        : "=l"(r) : "r"(__float_as_uint(a)), "r"(__float_as_uint(b)));
    return r;
}
__device__ __forceinline__ u64 ffma2(u64 a, u64 b, u64 c) {
    u64 d;
    asm("fma.rn.f32x2 %0, %1, %2, %3;" : "=l"(d) : "l"(a), "l"(b), "l"(c));
    return d;
}
__device__ __forceinline__ float2 unpack2(u64 v) {
    unsigned lo, hi;
    asm("mov.b64 {%0, %1}, %2;" : "=r"(lo), "=r"(hi) : "l"(v));
    return make_float2(__uint_as_float(lo), __uint_as_float(hi));
}

// ---------------------------------------------------------------------------
// Kernel 2: 3x3 conv, pad 1, NCHW. Block = 64 oc x 64 px (one output row).
// ---------------------------------------------------------------------------
__global__ __launch_bounds__(256, 3)
void conv_lora_kernel(const float* __restrict__ x,
                      const float* __restrict__ bias,
                      float* __restrict__ out) {
    __shared__ __align__(16) float sIn[CH][3][68];   // [c][row][col 0..65], col j = out px j-1
    __shared__ __align__(16) float sW[CH][9][64];    // [c][kh*3+kw][oc in tile]

    const int h   = blockIdx.x;         // 0..63
    const int n   = blockIdx.y;         // 0..15
    const int ocb = blockIdx.z * 64;    // 0,64,128,192

    const int tid = threadIdx.x;
    const int tx  = tid & 15;           // pixel group (4 px each)
    const int ty  = tid >> 4;           // oc group   (4 oc each)
    const int tx4 = tx * 4;
    const int ocl = ty * 4;

    // bias-initialized accumulators, packed over oc: acc0 = (oc+0, oc+1), acc1 = (oc+2, oc+3)
    const float b0 = bias[ocb + ocl + 0];
    const float b1 = bias[ocb + ocl + 1];
    const float b2 = bias[ocb + ocl + 2];
    const float b3 = bias[ocb + ocl + 3];
    u64 acc0[4], acc1[4];
    {
        u64 i01 = pack2(b0, b1), i23 = pack2(b2, b3);
#pragma unroll
        for (int p = 0; p < 4; ++p) { acc0[p] = i01; acc1[p] = i23; }
    }

    for (int cb = 0; cb < C_IN; cb += CH) {
        __syncthreads();   // protect previous stage's smem before overwrite

        // ---- stage input slab: CH channels x 3 rows x 66 cols (zero-padded) ----
        for (int idx = tid; idx < CH * 3 * 66; idx += 256) {
            int c   = idx / 198;
            int rem = idx - c * 198;
            int r   = rem / 66;
            int j   = rem - r * 66;
            int hh  = h + r - 1;
            int col = j - 1;
            float v = 0.f;
            if ((unsigned)hh < 64u && (unsigned)col < 64u)
                v = x[(((n * C_IN) + cb + c) * HW + hh) * HW + col];
            sIn[c][r][j] = v;
        }
        // ---- stage weight chunk: CH x 9 x 64 oc (contiguous rows of g_weffT) ----
        {
            float* sWf = &sW[0][0][0];
            for (int idx = tid; idx < CH * 9 * 64; idx += 256) {
                int row = idx >> 6;    // c*9 + k (local)
                int col = idx & 63;
                sWf[idx] = g_weffT[(cb * 9 + row) * C_OUT + ocb + col];
            }
        }
        __syncthreads();

        // ---- compute ----
#pragma unroll 2
        for (int c = 0; c < CH; ++c) {
#pragma unroll
            for (int kh = 0; kh < 3; ++kh) {
                const float* inRow = sIn[c][kh];
                float4 v4 = *(const float4*)(inRow + tx4);
                float  i4 = inRow[tx4 + 4];
                float  i5 = inRow[tx4 + 5];
                u64 ind[6];
                ind[0] = pack2(v4.x, v4.x);
                ind[1] = pack2(v4.y, v4.y);
                ind[2] = pack2(v4.z, v4.z);
                ind[3] = pack2(v4.w, v4.w);
                ind[4] = pack2(i4, i4);
                ind[5] = pack2(i5, i5);
#pragma unroll
                for (int kw = 0; kw < 3; ++kw) {
                    float4 w4 = *(const float4*)(sW[c][kh * 3 + kw] + ocl);
                    u64 w01 = pack2(w4.x, w4.y);
                    u64 w23 = pack2(w4.z, w4.w);
#pragma unroll
                    for (int p = 0; p < 4; ++p) {
                        acc0[p] = ffma2(w01, ind[p + kw], acc0[p]);
                        acc1[p] = ffma2(w23, ind[p + kw], acc1[p]);
                    }
                }
            }
        }
    }

    // ---- epilogue: unpack and store 4 oc x 4 px per thread (float4 stores) ----
    float4 r0, r1, r2, r3;
    {
        float2 a, b;
        a = unpack2(acc0[0]); b = unpack2(acc1[0]); r0.x = a.x; r1.x = a.y; r2.x = b.x; r3.x = b.y;
        a = unpack2(acc0[1]); b = unpack2(acc1[1]); r0.y = a.x; r1.y = a.y; r2.y = b.x; r3.y = b.y;
        a = unpack2(acc0[2]); b = unpack2(acc1[2]); r0.z = a.x; r1.z = a.y; r2.z = b.x; r3.z = b.y;
        a = unpack2(acc0[3]); b = unpack2(acc1[3]); r0.w = a.x; r1.w = a.y; r2.w = b.x; r3.w = b.y;
    }
    float* outp = out + (((size_t)(n * C_OUT + ocb + ocl) * HW + h) * HW) + tx4;
    *(float4*)(outp + 0 * HW * HW) = r0;
    *(float4*)(outp + 1 * HW * HW) = r1;
    *(float4*)(outp + 2 * HW * HW) = r2;
    *(float4*)(outp + 3 * HW * HW) = r3;
}

// ---------------------------------------------------------------------------
extern "C" void kernel_launch(void* const* d_in, const int* in_sizes, int n_in,
                              void* d_out, int out_size) {
    const float* x      = (const float*)d_in[0];   // [16,128,64,64]
    const float* W      = (const float*)d_in[1];   // [256,128,3,3]
    const float* b      = (const float*)d_in[2];   // [256]
    const float* lora_A = (const float*)d_in[3];   // [8,1152]
    const float* lora_B = (const float*)d_in[4];   // [256,8]
    float* out = (float*)d_out;                    // [16,256,64,64]

    fuse_weights_kernel<<<(C_OUT * KDIM + 255) / 256, 256>>>(W, lora_A, lora_B);

    dim3 grid(HW, NBATCH, C_OUT / 64);             // (64, 16, 4)
    conv_lora_kernel<<<grid, 256>>>(x, b, out);
}

// round 5
// speedup vs baseline: 4.0262x; 4.0262x over previous
#include <cuda_runtime.h>
#include <cuda_fp16.h>
#include <cstdint>
#include <cstddef>

#define C_IN    128
#define C_OUT   256
#define HWD     64
#define KDIM    1152                  // 128*9
#define M_TOTAL 65536                 // 16*64*64
#define KC      32                    // K per stage
#define KITER   (KDIM / KC)           // 36
#define STAGES  3

// smem geometry (halves)
#define SA      136                   // A tile row stride (k-major rows of 128 m + pad 8)
#define SB      40                    // B tile row stride (n rows of 32 k + pad 8)
#define A_STAGE_B (KC * SA * 2)       // 8704 B
#define B_STAGE_B (128 * SB * 2)      // 10240 B
#define AB_OFF  (STAGES * A_STAGE_B)  // 26112
#define SMEM_TOTAL (AB_OFF + STAGES * B_STAGE_B)   // 56832

// ---------------- scratch ----------------
__device__ __half g_At[(size_t)KDIM * M_TOTAL];   // im2col^T, fp16 (151MB)
__device__ __half g_Bh[(size_t)C_OUT * KDIM];     // fused weights, fp16

// ---------------- helpers ----------------
__device__ __forceinline__ uint32_t smem_u32(const void* p) {
    uint32_t a;
    asm("{ .reg .u64 t; cvta.to.shared.u64 t, %1; cvt.u32.u64 %0, t; }" : "=r"(a) : "l"(p));
    return a;
}
__device__ __forceinline__ void cpasync16(uint32_t dst, const void* src) {
    asm volatile("cp.async.cg.shared.global [%0], [%1], 16;" :: "r"(dst), "l"(src) : "memory");
}
__device__ __forceinline__ void cp_commit() { asm volatile("cp.async.commit_group;" ::: "memory"); }
__device__ __forceinline__ void cp_wait1()  { asm volatile("cp.async.wait_group 1;" ::: "memory"); }
__device__ __forceinline__ void cp_wait0()  { asm volatile("cp.async.wait_group 0;" ::: "memory"); }

__device__ __forceinline__ void ldsm4_t(uint32_t* r, uint32_t addr) {
    asm volatile("ldmatrix.sync.aligned.m8n8.x4.trans.shared.b16 {%0,%1,%2,%3}, [%4];"
                 : "=r"(r[0]), "=r"(r[1]), "=r"(r[2]), "=r"(r[3]) : "r"(addr));
}
__device__ __forceinline__ void ldsm4(uint32_t* r, uint32_t addr) {
    asm volatile("ldmatrix.sync.aligned.m8n8.x4.shared.b16 {%0,%1,%2,%3}, [%4];"
                 : "=r"(r[0]), "=r"(r[1]), "=r"(r[2]), "=r"(r[3]) : "r"(addr));
}
__device__ __forceinline__ void mma16816(float* d, const uint32_t* a, const uint32_t* b) {
    asm volatile(
        "mma.sync.aligned.m16n8k16.row.col.f32.f16.f16.f32 "
        "{%0,%1,%2,%3}, {%4,%5,%6,%7}, {%8,%9}, {%0,%1,%2,%3};"
        : "+f"(d[0]), "+f"(d[1]), "+f"(d[2]), "+f"(d[3])
        : "r"(a[0]), "r"(a[1]), "r"(a[2]), "r"(a[3]), "r"(b[0]), "r"(b[1]));
}

// ---------------------------------------------------------------------------
// Kernel 1: fused weights fp16:  g_Bh[oc][k] = h(W[oc][k] + 2*sum_r B[oc,r]A[r,k])
// ---------------------------------------------------------------------------
__global__ void fuse_weights_kernel(const float* __restrict__ W,
                                    const float* __restrict__ lA,
                                    const float* __restrict__ lB) {
    int idx = blockIdx.x * 256 + threadIdx.x;        // 0..294911
    int o = idx / KDIM;
    int k = idx - o * KDIM;
    float s = 0.f;
#pragma unroll
    for (int r = 0; r < 8; ++r)
        s += lB[o * 8 + r] * lA[r * KDIM + k];
    g_Bh[idx] = __float2half_rn(W[idx] + 2.0f * s);
}

// ---------------------------------------------------------------------------
// Kernel 2: transposed im2col fp16: g_At[k][m], k=c*9+kh*3+kw, m=(n,h,w)
// Each thread: one k, 8 consecutive pixels (one uint4 store).
// ---------------------------------------------------------------------------
__global__ void im2col_kernel(const float* __restrict__ x) {
    const int k  = blockIdx.y;                        // 0..1151
    const int m0 = (blockIdx.x * 256 + threadIdx.x) * 8;   // 0..65528
    const int c  = k / 9;
    const int r  = k - c * 9;
    const int kh = r / 3, kw = r - kh * 3;

    const int n  = m0 >> 12;
    const int h  = (m0 >> 6) & 63;
    const int w0 = m0 & 63;                           // multiple of 8
    const int hh = h + kh - 1;

    __half v[8];
    if ((unsigned)hh < 64u) {
        const float* xr = x + (((size_t)(n * C_IN + c)) * HWD + hh) * HWD;
#pragma unroll
        for (int i = 0; i < 8; ++i) {
            int ww = w0 + i + kw - 1;
            v[i] = __float2half_rn(((unsigned)ww < 64u) ? xr[ww] : 0.f);
        }
    } else {
#pragma unroll
        for (int i = 0; i < 8; ++i) v[i] = __float2half_rn(0.f);
    }
    *(uint4*)&g_At[(size_t)k * M_TOTAL + m0] = *(const uint4*)v;
}

// ---------------------------------------------------------------------------
// Kernel 3: GEMM  out[m, oc] = A[:,m] . B[oc,:] + bias[oc]
// CTA 128M x 128N, 8 warps (2M x 4N -> warp 64M x 32N), 3-stage cp.async.
// ---------------------------------------------------------------------------
__device__ __forceinline__ void load_stage(uint32_t sm, int it, int m0, int oc0, int tid) {
    const int s  = it % STAGES;
    const int k0 = it * KC;
    // A: 32 k-rows x 128 m (16 chunks of 8 halves per row)
#pragma unroll
    for (int i = 0; i < 2; ++i) {
        int idx = tid + i * 256;                      // 0..511
        int kr  = idx >> 4;                           // 0..31
        int mc  = idx & 15;                           // 0..15
        cpasync16(sm + s * A_STAGE_B + kr * (SA * 2) + mc * 16,
                  &g_At[(size_t)(k0 + kr) * M_TOTAL + m0 + mc * 8]);
    }
    // B: 128 n-rows x 32 k (4 chunks per row)
#pragma unroll
    for (int i = 0; i < 2; ++i) {
        int idx = tid + i * 256;
        int n   = idx >> 2;                           // 0..127
        int kc  = idx & 3;                            // 0..3
        cpasync16(sm + AB_OFF + s * B_STAGE_B + n * (SB * 2) + kc * 16,
                  &g_Bh[(size_t)(oc0 + n) * KDIM + k0 + kc * 8]);
    }
    cp_commit();
}

__global__ __launch_bounds__(256, 1)
void gemm_fp16_kernel(const float* __restrict__ bias, float* __restrict__ out) {
    extern __shared__ __align__(16) char smem[];
    const uint32_t sm = smem_u32(smem);

    const int tid  = threadIdx.x;
    const int wid  = tid >> 5;
    const int lane = tid & 31;
    const int oc0  = blockIdx.x * 128;                // 0 or 128 (fastest -> L2 A reuse)
    const int m0   = blockIdx.y * 128;

    const int wm = wid & 1;                           // 0..1  (64 m each)
    const int wn = wid >> 1;                          // 0..3  (32 n each)
    const int grp   = lane >> 3;                      // ldmatrix address group
    const int l7    = lane & 7;

    float acc[4][4][4];
#pragma unroll
    for (int i = 0; i < 4; ++i)
#pragma unroll
        for (int j = 0; j < 4; ++j)
#pragma unroll
            for (int p = 0; p < 4; ++p) acc[i][j][p] = 0.f;

    load_stage(sm, 0, m0, oc0, tid);
    load_stage(sm, 1, m0, oc0, tid);

    for (int it = 0; it < KITER; ++it) {
        const int s = it % STAGES;
        if (it < KITER - 1) cp_wait1(); else cp_wait0();
        __syncthreads();
        if (it + 2 < KITER) load_stage(sm, it + 2, m0, oc0, tid);

        const uint32_t aBase = sm + s * A_STAGE_B;
        const uint32_t bBase = sm + AB_OFF + s * B_STAGE_B;

#pragma unroll
        for (int ks = 0; ks < 2; ++ks) {
            // A fragments: trans ldmatrix on k-major tile
            // k = ks*16 + (grp>>1)*8 + l7 ; m = wm*64 + i*16 + (grp&1)*8
            uint32_t a[4][4];
            const uint32_t aK = (uint32_t)(ks * 16 + (grp >> 1) * 8 + l7) * (SA * 2);
#pragma unroll
            for (int i = 0; i < 4; ++i) {
                uint32_t addr = aBase + aK + (uint32_t)(wm * 64 + i * 16 + (grp & 1) * 8) * 2;
                ldsm4_t(a[i], addr);
            }
            // B fragments: plain ldmatrix on [n][k]
            // n = wn*32 + half*16 + (grp>>1)*8 + l7 ; k = ks*16 + (grp&1)*8
            uint32_t b[4][2];
#pragma unroll
            for (int half = 0; half < 2; ++half) {
                uint32_t r[4];
                uint32_t addr = bBase
                    + (uint32_t)(wn * 32 + half * 16 + (grp >> 1) * 8 + l7) * (SB * 2)
                    + (uint32_t)(ks * 16 + (grp & 1) * 8) * 2;
                ldsm4(r, addr);
                b[half * 2 + 0][0] = r[0]; b[half * 2 + 0][1] = r[1];
                b[half * 2 + 1][0] = r[2]; b[half * 2 + 1][1] = r[3];
            }
#pragma unroll
            for (int i = 0; i < 4; ++i)
#pragma unroll
                for (int j = 0; j < 4; ++j)
                    mma16816(acc[i][j], a[i], b[j]);
        }
    }

    // epilogue: d0,d1 -> (row=g, col=2c,2c+1); d2,d3 -> row g+8
    const int g  = lane >> 2;
    const int c2 = (lane & 3) * 2;
    float bia[4][2];
#pragma unroll
    for (int j = 0; j < 4; ++j) {
        int oc = oc0 + wn * 32 + j * 8 + c2;
        bia[j][0] = __ldg(bias + oc);
        bia[j][1] = __ldg(bias + oc + 1);
    }
#pragma unroll
    for (int i = 0; i < 4; ++i) {
#pragma unroll
        for (int rr = 0; rr < 2; ++rr) {
            int m  = m0 + wm * 64 + i * 16 + g + rr * 8;
            size_t base = (size_t)(m >> 12) * ((size_t)C_OUT * 4096) + (m & 4095);
#pragma unroll
            for (int j = 0; j < 4; ++j) {
                int oc = oc0 + wn * 32 + j * 8 + c2;
                out[base + (size_t)oc * 4096]       = acc[i][j][rr * 2 + 0] + bia[j][0];
                out[base + (size_t)(oc + 1) * 4096] = acc[i][j][rr * 2 + 1] + bia[j][1];
            }
        }
    }
}

// ---------------------------------------------------------------------------
extern "C" void kernel_launch(void* const* d_in, const int* in_sizes, int n_in,
                              void* d_out, int out_size) {
    const float* x      = (const float*)d_in[0];   // [16,128,64,64]
    const float* W      = (const float*)d_in[1];   // [256,128,3,3]
    const float* b      = (const float*)d_in[2];   // [256]
    const float* lora_A = (const float*)d_in[3];   // [8,1152]
    const float* lora_B = (const float*)d_in[4];   // [256,8]
    float* out = (float*)d_out;                    // [16,256,64,64]

    static int smem_set = 0;
    if (!smem_set) {
        cudaFuncSetAttribute(gemm_fp16_kernel,
                             cudaFuncAttributeMaxDynamicSharedMemorySize, SMEM_TOTAL);
        smem_set = 1;
    }

    fuse_weights_kernel<<<(C_OUT * KDIM) / 256, 256>>>(W, lora_A, lora_B);
    im2col_kernel<<<dim3(M_TOTAL / 8 / 256, KDIM), 256>>>(x);
    gemm_fp16_kernel<<<dim3(2, M_TOTAL / 128), 256, SMEM_TOTAL>>>(b, out);
}

// round 6
// speedup vs baseline: 5.3628x; 1.3320x over previous
#include <cuda_runtime.h>
#include <cuda_fp16.h>
#include <cstdint>
#include <cstddef>

#define C_IN    128
#define C_OUT   256
#define HWD     64
#define KDIM    1152                  // 9 taps * 128 ch, k = tap*128 + c
#define M_TOTAL 65536                 // 16*64*64
#define KC      32                    // K per stage (one tap, 32 channels)
#define KITER   (KDIM / KC)           // 36
#define STAGES  4

// smem rows padded to 80B (40 halves) -> conflict-free ldmatrix
#define A_ST    (128 * 80)            // 10240 B / stage
#define B_ST    (256 * 80)            // 20480 B / stage
#define B_OFF   (STAGES * A_ST)       // 40960
#define SMEM_TOTAL (B_OFF + STAGES * B_ST)   // 122880

// ---------------- scratch ----------------
__device__ __half g_xh[(size_t)M_TOTAL * C_IN];   // x in NHWC fp16 (16.8MB, L2-resident)
__device__ __half g_Bt[(size_t)C_OUT * KDIM];     // fused weights, [oc][tap*128+c]

// ---------------- helpers ----------------
__device__ __forceinline__ uint32_t smem_u32(const void* p) {
    uint32_t a;
    asm("{ .reg .u64 t; cvta.to.shared.u64 t, %1; cvt.u32.u64 %0, t; }" : "=r"(a) : "l"(p));
    return a;
}
__device__ __forceinline__ void cpasync16(uint32_t dst, const void* src) {
    asm volatile("cp.async.cg.shared.global [%0], [%1], 16;" :: "r"(dst), "l"(src) : "memory");
}
// zero-fill variant: src_sz = 0 -> writes zeros (border pixels)
__device__ __forceinline__ void cpasync16z(uint32_t dst, const void* src, uint32_t src_sz) {
    asm volatile("cp.async.cg.shared.global [%0], [%1], 16, %2;"
                 :: "r"(dst), "l"(src), "r"(src_sz) : "memory");
}
__device__ __forceinline__ void cp_commit() { asm volatile("cp.async.commit_group;" ::: "memory"); }
__device__ __forceinline__ void cp_wait2()  { asm volatile("cp.async.wait_group 2;" ::: "memory"); }
__device__ __forceinline__ void cp_wait0()  { asm volatile("cp.async.wait_group 0;" ::: "memory"); }

__device__ __forceinline__ void ldsm4(uint32_t* r, uint32_t addr) {
    asm volatile("ldmatrix.sync.aligned.m8n8.x4.shared.b16 {%0,%1,%2,%3}, [%4];"
                 : "=r"(r[0]), "=r"(r[1]), "=r"(r[2]), "=r"(r[3]) : "r"(addr));
}
__device__ __forceinline__ void mma16816(float* d, const uint32_t* a, const uint32_t* b) {
    asm volatile(
        "mma.sync.aligned.m16n8k16.row.col.f32.f16.f16.f32 "
        "{%0,%1,%2,%3}, {%4,%5,%6,%7}, {%8,%9}, {%0,%1,%2,%3};"
        : "+f"(d[0]), "+f"(d[1]), "+f"(d[2]), "+f"(d[3])
        : "r"(a[0]), "r"(a[1]), "r"(a[2]), "r"(a[3]), "r"(b[0]), "r"(b[1]));
}

// ---------------------------------------------------------------------------
// Kernel 1: fused weights, permuted to tap-major K.
//   g_Bt[oc][tap*128+c] = h( W[oc][c*9+tap] + 2*sum_r lB[oc,r]*lA[r, c*9+tap] )
// ---------------------------------------------------------------------------
__global__ void fuse_weights_kernel(const float* __restrict__ W,
                                    const float* __restrict__ lA,
                                    const float* __restrict__ lB) {
    int idx = blockIdx.x * 256 + threadIdx.x;        // 0..294911, = oc*1152 + c*9 + tap
    int oc  = idx / KDIM;
    int rem = idx - oc * KDIM;
    int c   = rem / 9;
    int tap = rem - c * 9;
    float s = 0.f;
#pragma unroll
    for (int r = 0; r < 8; ++r)
        s += lB[oc * 8 + r] * lA[r * KDIM + rem];
    g_Bt[(size_t)oc * KDIM + tap * 128 + c] = __float2half_rn(W[idx] + 2.0f * s);
}

// ---------------------------------------------------------------------------
// Kernel 2: NCHW fp32 -> NHWC fp16. One block per (n, h): 128c x 64w tile.
// ---------------------------------------------------------------------------
__global__ __launch_bounds__(256)
void nhwc_kernel(const float* __restrict__ x) {
    __shared__ float sT[128][65];
    const int n = blockIdx.x >> 6;
    const int h = blockIdx.x & 63;
    const int tid = threadIdx.x;

    const float* xp = x + ((size_t)n * C_IN * HWD + h) * HWD;   // + c*4096 + w
#pragma unroll
    for (int i = 0; i < 32; ++i) {
        int idx = i * 256 + tid;
        int c = idx >> 6, w = idx & 63;
        sT[c][w] = xp[(size_t)c * (HWD * HWD) + w];
    }
    __syncthreads();

    __half* dst = g_xh + ((size_t)(n * 64 + h) * 64) * C_IN;    // + w*128 + c
#pragma unroll
    for (int i = 0; i < 16; ++i) {
        int idx = i * 256 + tid;
        int w = idx >> 6, cp = idx & 63;
        int c = cp * 2;
        __half2 v = __floats2half2_rn(sT[c][w], sT[c + 1][w]);
        *(__half2*)(dst + (size_t)w * C_IN + c) = v;
    }
}

// ---------------------------------------------------------------------------
// Kernel 3: implicit-conv GEMM. CTA: 128 m (2 h-rows x 64 w) x 256 oc.
// A-tile rows load directly from NHWC x with tap shift + zero-fill borders.
// ---------------------------------------------------------------------------
__device__ __forceinline__ void load_stage(uint32_t sm, int it, int m0, int tid) {
    const int s   = it & 3;           // it % STAGES
    const int tap = it >> 2;          // 128/KC = 4 chunks per tap
    const int c0  = (it & 3) * 32;    // channel chunk within tap
    const int kh  = tap / 3;
    const int kw  = tap - kh * 3;
    const int n   = m0 >> 12;
    const int h0  = (m0 >> 6) & 63;

    // A: 128 rows x 64B (32 ch), 4 x 16B chunks per row
#pragma unroll
    for (int i = 0; i < 2; ++i) {
        int idx = tid + i * 256;                      // 0..511
        int r   = idx >> 2;                           // m row 0..127
        int q   = idx & 3;
        int hh  = h0 + (r >> 6) + kh - 1;
        int ww  = (r & 63) + kw - 1;
        bool ok = ((unsigned)hh < 64u) && ((unsigned)ww < 64u);
        const __half* src = ok
            ? &g_xh[(size_t)(((n * 64 + hh) * 64) + ww) * C_IN + c0 + q * 8]
            : &g_xh[0];
        cpasync16z(sm + s * A_ST + r * 80 + q * 16, src, ok ? 16u : 0u);
    }
    // B: 256 oc rows x 64B
#pragma unroll
    for (int i = 0; i < 4; ++i) {
        int idx = tid + i * 256;                      // 0..1023
        int r   = idx >> 2;                           // oc 0..255
        int q   = idx & 3;
        cpasync16(sm + B_OFF + s * B_ST + r * 80 + q * 16,
                  &g_Bt[(size_t)r * KDIM + tap * 128 + c0 + q * 8]);
    }
    cp_commit();
}

__global__ __launch_bounds__(256, 1)
void gemm_kernel(const float* __restrict__ bias, float* __restrict__ out) {
    extern __shared__ __align__(16) char smem[];
    const uint32_t sm = smem_u32(smem);

    const int tid  = threadIdx.x;
    const int wid  = tid >> 5;
    const int lane = tid & 31;
    const int m0   = blockIdx.x * 128;

    const int wm  = wid & 1;          // 0..1, 64 m each
    const int wn  = wid >> 1;         // 0..3, 64 oc each
    const int grp = lane >> 3;
    const int l7  = lane & 7;

    float acc[4][8][4];
#pragma unroll
    for (int i = 0; i < 4; ++i)
#pragma unroll
        for (int j = 0; j < 8; ++j)
#pragma unroll
            for (int p = 0; p < 4; ++p) acc[i][j][p] = 0.f;

    load_stage(sm, 0, m0, tid);
    load_stage(sm, 1, m0, tid);
    load_stage(sm, 2, m0, tid);

    for (int it = 0; it < KITER; ++it) {
        const int s = it & 3;
        if (it < KITER - 3) cp_wait2(); else cp_wait0();
        __syncthreads();
        if (it + 3 < KITER) load_stage(sm, it + 3, m0, tid);

        const uint32_t aBase = sm + s * A_ST;
        const uint32_t bBase = sm + B_OFF + s * B_ST;

#pragma unroll
        for (int ks = 0; ks < 2; ++ks) {
            // B frags: 4 x ldsm.x4 covering 64 oc x 16 k
            uint32_t b[8][2];
#pragma unroll
            for (int half = 0; half < 4; ++half) {
                uint32_t r[4];
                uint32_t addr = bBase
                    + (uint32_t)(wn * 64 + half * 16 + (grp >> 1) * 8 + l7) * 80
                    + (uint32_t)((grp & 1) * 8 + ks * 16) * 2;
                ldsm4(r, addr);
                b[half * 2 + 0][0] = r[0]; b[half * 2 + 0][1] = r[1];
                b[half * 2 + 1][0] = r[2]; b[half * 2 + 1][1] = r[3];
            }
            // A frags: rows (lane&15), k-col (lane>>4)
#pragma unroll
            for (int i = 0; i < 4; ++i) {
                uint32_t a[4];
                uint32_t addr = aBase
                    + (uint32_t)(wm * 64 + i * 16 + (lane & 15)) * 80
                    + (uint32_t)((lane >> 4) * 8 + ks * 16) * 2;
                ldsm4(a, addr);
#pragma unroll
                for (int j = 0; j < 8; ++j)
                    mma16816(acc[i][j], a, b[j]);
            }
        }
    }

    // epilogue: d0,d1 -> (m=g, oc=c2,c2+1); d2,d3 -> m=g+8
    const int g  = lane >> 2;
    const int c2 = (lane & 3) * 2;
    const int n  = m0 >> 12;
    float bia[8][2];
#pragma unroll
    for (int j = 0; j < 8; ++j) {
        int oc = wn * 64 + j * 8 + c2;
        bia[j][0] = __ldg(bias + oc);
        bia[j][1] = __ldg(bias + oc + 1);
    }
#pragma unroll
    for (int i = 0; i < 4; ++i) {
#pragma unroll
        for (int rr = 0; rr < 2; ++rr) {
            int m = m0 + wm * 64 + i * 16 + g + rr * 8;
            size_t base = (size_t)n * (C_OUT * 4096) + (m & 4095);
#pragma unroll
            for (int j = 0; j < 8; ++j) {
                int oc = wn * 64 + j * 8 + c2;
                out[base + (size_t)oc * 4096]       = acc[i][j][rr * 2 + 0] + bia[j][0];
                out[base + (size_t)(oc + 1) * 4096] = acc[i][j][rr * 2 + 1] + bia[j][1];
            }
        }
    }
}

// ---------------------------------------------------------------------------
extern "C" void kernel_launch(void* const* d_in, const int* in_sizes, int n_in,
                              void* d_out, int out_size) {
    const float* x      = (const float*)d_in[0];   // [16,128,64,64]
    const float* W      = (const float*)d_in[1];   // [256,128,3,3]
    const float* b      = (const float*)d_in[2];   // [256]
    const float* lora_A = (const float*)d_in[3];   // [8,1152]
    const float* lora_B = (const float*)d_in[4];   // [256,8]
    float* out = (float*)d_out;                    // [16,256,64,64]

    static int smem_set = 0;
    if (!smem_set) {
        cudaFuncSetAttribute(gemm_kernel,
                             cudaFuncAttributeMaxDynamicSharedMemorySize, SMEM_TOTAL);
        smem_set = 1;
    }

    fuse_weights_kernel<<<(C_OUT * KDIM) / 256, 256>>>(W, lora_A, lora_B);
    nhwc_kernel<<<16 * 64, 256>>>(x);
    gemm_kernel<<<M_TOTAL / 128, 256, SMEM_TOTAL>>>(b, out);
}

// round 7
// speedup vs baseline: 6.6181x; 1.2341x over previous
#include <cuda_runtime.h>
#include <cuda_fp16.h>
#include <cstdint>
#include <cstddef>

#define C_IN    128
#define C_OUT   256
#define HWD     64
#define KDIM    1152                  // 9 taps * 128 ch, k = tap*128 + c
#define M_TOTAL 65536                 // 16*64*64
#define KC      32
#define KITER   (KDIM / KC)           // 36
#define STAGES  4

// smem rows padded to 80B (40 halves) -> conflict-free ldmatrix
#define A_ST    (128 * 80)            // 10240 B / stage
#define B_ST    (128 * 80)            // 10240 B / stage
#define B_OFF   (STAGES * A_ST)       // 40960
#define SMEM_TOTAL (B_OFF + STAGES * B_ST)   // 81920 -> 2 CTAs/SM

// ---------------- scratch ----------------
__device__ __half g_xh[(size_t)M_TOTAL * C_IN];   // x in NHWC fp16 (16.8MB)
__device__ __half g_Bt[(size_t)C_OUT * KDIM];     // fused weights, [oc][tap*128+c]

// ---------------- helpers ----------------
__device__ __forceinline__ uint32_t smem_u32(const void* p) {
    uint32_t a;
    asm("{ .reg .u64 t; cvta.to.shared.u64 t, %1; cvt.u32.u64 %0, t; }" : "=r"(a) : "l"(p));
    return a;
}
__device__ __forceinline__ void cpasync16(uint32_t dst, const void* src) {
    asm volatile("cp.async.cg.shared.global [%0], [%1], 16;" :: "r"(dst), "l"(src) : "memory");
}
__device__ __forceinline__ void cpasync16z(uint32_t dst, const void* src, uint32_t src_sz) {
    asm volatile("cp.async.cg.shared.global [%0], [%1], 16, %2;"
                 :: "r"(dst), "l"(src), "r"(src_sz) : "memory");
}
__device__ __forceinline__ void cp_commit() { asm volatile("cp.async.commit_group;" ::: "memory"); }
__device__ __forceinline__ void cp_wait2()  { asm volatile("cp.async.wait_group 2;" ::: "memory"); }
__device__ __forceinline__ void cp_wait0()  { asm volatile("cp.async.wait_group 0;" ::: "memory"); }

__device__ __forceinline__ void ldsm4(uint32_t* r, uint32_t addr) {
    asm volatile("ldmatrix.sync.aligned.m8n8.x4.shared.b16 {%0,%1,%2,%3}, [%4];"
                 : "=r"(r[0]), "=r"(r[1]), "=r"(r[2]), "=r"(r[3]) : "r"(addr));
}
__device__ __forceinline__ void mma16816(float* d, const uint32_t* a, const uint32_t* b) {
    asm volatile(
        "mma.sync.aligned.m16n8k16.row.col.f32.f16.f16.f32 "
        "{%0,%1,%2,%3}, {%4,%5,%6,%7}, {%8,%9}, {%0,%1,%2,%3};"
        : "+f"(d[0]), "+f"(d[1]), "+f"(d[2]), "+f"(d[3])
        : "r"(a[0]), "r"(a[1]), "r"(a[2]), "r"(a[3]), "r"(b[0]), "r"(b[1]));
}

// ---------------------------------------------------------------------------
// Kernel 1 (merged prologue):
//   blocks [0,1024):    NCHW fp32 -> NHWC fp16 transpose (one (n,h) row each)
//   blocks [1024,2176): fused weights, permuted to tap-major K
// ---------------------------------------------------------------------------
__global__ __launch_bounds__(256)
void prologue_kernel(const float* __restrict__ x,
                     const float* __restrict__ W,
                     const float* __restrict__ lA,
                     const float* __restrict__ lB) {
    const int tid = threadIdx.x;
    if (blockIdx.x < 1024) {
        __shared__ float sT[128][65];
        const int n = blockIdx.x >> 6;
        const int h = blockIdx.x & 63;
        const float* xp = x + ((size_t)n * C_IN * HWD + h) * HWD;
#pragma unroll
        for (int i = 0; i < 32; ++i) {
            int idx = i * 256 + tid;
            int c = idx >> 6, w = idx & 63;
            sT[c][w] = xp[(size_t)c * (HWD * HWD) + w];
        }
        __syncthreads();
        __half* dst = g_xh + ((size_t)(n * 64 + h) * 64) * C_IN;
#pragma unroll
        for (int i = 0; i < 16; ++i) {
            int idx = i * 256 + tid;
            int w = idx >> 6, c = (idx & 63) * 2;
            __half2 v = __floats2half2_rn(sT[c][w], sT[c + 1][w]);
            *(__half2*)(dst + (size_t)w * C_IN + c) = v;
        }
    } else {
        int idx = (blockIdx.x - 1024) * 256 + tid;   // oc*1152 + c*9 + tap
        int oc  = idx / KDIM;
        int rem = idx - oc * KDIM;
        int c   = rem / 9;
        int tap = rem - c * 9;
        float s = 0.f;
#pragma unroll
        for (int r = 0; r < 8; ++r)
            s += lB[oc * 8 + r] * lA[r * KDIM + rem];
        g_Bt[(size_t)oc * KDIM + tap * 128 + c] = __float2half_rn(W[idx] + 2.0f * s);
    }
}

// ---------------------------------------------------------------------------
// Kernel 2: implicit-conv GEMM. CTA 128m x 128oc, occupancy 2.
// ---------------------------------------------------------------------------
__device__ __forceinline__ void load_stage(uint32_t sm, int it, int m0, int oc0, int tid) {
    const int s   = it & 3;
    const int tap = it >> 2;          // 4 channel-chunks per tap
    const int c0  = (it & 3) * 32;
    const int kh  = tap / 3;
    const int kw  = tap - kh * 3;
    const int n   = m0 >> 12;
    const int h0  = (m0 >> 6) & 63;

    // A: 128 m-rows x 64B
#pragma unroll
    for (int i = 0; i < 2; ++i) {
        int idx = tid + i * 256;                      // 0..511
        int r   = idx >> 2;
        int q   = idx & 3;
        int hh  = h0 + (r >> 6) + kh - 1;
        int ww  = (r & 63) + kw - 1;
        bool ok = ((unsigned)hh < 64u) && ((unsigned)ww < 64u);
        const __half* src = ok
            ? &g_xh[(size_t)(((n * 64 + hh) * 64) + ww) * C_IN + c0 + q * 8]
            : &g_xh[0];
        cpasync16z(sm + s * A_ST + r * 80 + q * 16, src, ok ? 16u : 0u);
    }
    // B: 128 oc-rows x 64B
#pragma unroll
    for (int i = 0; i < 2; ++i) {
        int idx = tid + i * 256;
        int r   = idx >> 2;
        int q   = idx & 3;
        cpasync16(sm + B_OFF + s * B_ST + r * 80 + q * 16,
                  &g_Bt[(size_t)(oc0 + r) * KDIM + tap * 128 + c0 + q * 8]);
    }
    cp_commit();
}

__global__ __launch_bounds__(256, 2)
void gemm_kernel(const float* __restrict__ bias, float* __restrict__ out) {
    extern __shared__ __align__(16) char smem[];
    const uint32_t sm = smem_u32(smem);

    const int tid  = threadIdx.x;
    const int wid  = tid >> 5;
    const int lane = tid & 31;
    const int oc0  = blockIdx.x * 128;   // fastest -> A tile shared in L2
    const int m0   = blockIdx.y * 128;

    const int wm  = wid & 1;          // 64 m per warp
    const int wn  = wid >> 1;         // 32 oc per warp
    const int grp = lane >> 3;
    const int l7  = lane & 7;

    float acc[4][4][4];
#pragma unroll
    for (int i = 0; i < 4; ++i)
#pragma unroll
        for (int j = 0; j < 4; ++j)
#pragma unroll
            for (int p = 0; p < 4; ++p) acc[i][j][p] = 0.f;

    load_stage(sm, 0, m0, oc0, tid);
    load_stage(sm, 1, m0, oc0, tid);
    load_stage(sm, 2, m0, oc0, tid);

    for (int it = 0; it < KITER; ++it) {
        const int s = it & 3;
        if (it < KITER - 3) cp_wait2(); else cp_wait0();
        __syncthreads();
        if (it + 3 < KITER) load_stage(sm, it + 3, m0, oc0, tid);

        const uint32_t aBase = sm + s * A_ST;
        const uint32_t bBase = sm + B_OFF + s * B_ST;

#pragma unroll
        for (int ks = 0; ks < 2; ++ks) {
            // B frags: 2 ldsm.x4 -> 32 oc x 16 k
            uint32_t b[4][2];
#pragma unroll
            for (int half = 0; half < 2; ++half) {
                uint32_t r[4];
                uint32_t addr = bBase
                    + (uint32_t)(wn * 32 + half * 16 + (grp >> 1) * 8 + l7) * 80
                    + (uint32_t)((grp & 1) * 8 + ks * 16) * 2;
                ldsm4(r, addr);
                b[half * 2 + 0][0] = r[0]; b[half * 2 + 0][1] = r[1];
                b[half * 2 + 1][0] = r[2]; b[half * 2 + 1][1] = r[3];
            }
            // A frags: 4 ldsm.x4 -> 64 m x 16 k
#pragma unroll
            for (int i = 0; i < 4; ++i) {
                uint32_t a[4];
                uint32_t addr = aBase
                    + (uint32_t)(wm * 64 + i * 16 + (lane & 15)) * 80
                    + (uint32_t)((lane >> 4) * 8 + ks * 16) * 2;
                ldsm4(a, addr);
#pragma unroll
                for (int j = 0; j < 4; ++j)
                    mma16816(acc[i][j], a, b[j]);
            }
        }
    }

    // epilogue
    const int g  = lane >> 2;
    const int c2 = (lane & 3) * 2;
    const int n  = m0 >> 12;
    float bia[4][2];
#pragma unroll
    for (int j = 0; j < 4; ++j) {
        int oc = oc0 + wn * 32 + j * 8 + c2;
        bia[j][0] = __ldg(bias + oc);
        bia[j][1] = __ldg(bias + oc + 1);
    }
#pragma unroll
    for (int i = 0; i < 4; ++i) {
#pragma unroll
        for (int rr = 0; rr < 2; ++rr) {
            int m = m0 + wm * 64 + i * 16 + g + rr * 8;
            size_t base = (size_t)n * (C_OUT * 4096) + (m & 4095);
#pragma unroll
            for (int j = 0; j < 4; ++j) {
                int oc = oc0 + wn * 32 + j * 8 + c2;
                out[base + (size_t)oc * 4096]       = acc[i][j][rr * 2 + 0] + bia[j][0];
                out[base + (size_t)(oc + 1) * 4096] = acc[i][j][rr * 2 + 1] + bia[j][1];
            }
        }
    }
}

// ---------------------------------------------------------------------------
extern "C" void kernel_launch(void* const* d_in, const int* in_sizes, int n_in,
                              void* d_out, int out_size) {
    const float* x      = (const float*)d_in[0];
    const float* W      = (const float*)d_in[1];
    const float* b      = (const float*)d_in[2];
    const float* lora_A = (const float*)d_in[3];
    const float* lora_B = (const float*)d_in[4];
    float* out = (float*)d_out;

    static int smem_set = 0;
    if (!smem_set) {
        cudaFuncSetAttribute(gemm_kernel,
                             cudaFuncAttributeMaxDynamicSharedMemorySize, SMEM_TOTAL);
        smem_set = 1;
    }

    prologue_kernel<<<1024 + (C_OUT * KDIM) / 256, 256>>>(x, W, lora_A, lora_B);
    gemm_kernel<<<dim3(2, M_TOTAL / 128), 256, SMEM_TOTAL>>>(b, out);
}

// round 8
// speedup vs baseline: 6.8090x; 1.0288x over previous
#include <cuda_runtime.h>
#include <cuda_fp16.h>
#include <cstdint>
#include <cstddef>

#define C_IN    128
#define C_OUT   256
#define HWD     64
#define KDIM    1152                  // 9 taps * 128 ch, k = tap*128 + c
#define M_TOTAL 65536                 // 16*64*64
#define KC      32
#define KITER   (KDIM / KC)           // 36
#define STAGES  4

#define A_ST    (128 * 80)            // 10240 B / stage
#define B_ST    (128 * 80)            // 10240 B / stage
#define B_OFF   (STAGES * A_ST)       // 40960
#define SMEM_TOTAL (B_OFF + STAGES * B_ST)   // 81920 -> 2 CTAs/SM

// ---------------- scratch ----------------
__device__ __half g_xh[(size_t)M_TOTAL * C_IN];   // x in NHWC fp16 (16.8MB)
__device__ __half g_Bt[(size_t)C_OUT * KDIM];     // fused weights, [oc][tap*128+c]

// ---------------- helpers ----------------
__device__ __forceinline__ uint32_t smem_u32(const void* p) {
    uint32_t a;
    asm("{ .reg .u64 t; cvta.to.shared.u64 t, %1; cvt.u32.u64 %0, t; }" : "=r"(a) : "l"(p));
    return a;
}
__device__ __forceinline__ void cpasync16(uint32_t dst, const void* src) {
    asm volatile("cp.async.cg.shared.global [%0], [%1], 16;" :: "r"(dst), "l"(src) : "memory");
}
__device__ __forceinline__ void cpasync16z(uint32_t dst, const void* src, uint32_t src_sz) {
    asm volatile("cp.async.cg.shared.global [%0], [%1], 16, %2;"
                 :: "r"(dst), "l"(src), "r"(src_sz) : "memory");
}
__device__ __forceinline__ void cp_commit() { asm volatile("cp.async.commit_group;" ::: "memory"); }
__device__ __forceinline__ void cp_wait1()  { asm volatile("cp.async.wait_group 1;" ::: "memory"); }
__device__ __forceinline__ void cp_wait0()  { asm volatile("cp.async.wait_group 0;" ::: "memory"); }

__device__ __forceinline__ void ldsm4(uint32_t* r, uint32_t addr) {
    asm volatile("ldmatrix.sync.aligned.m8n8.x4.shared.b16 {%0,%1,%2,%3}, [%4];"
                 : "=r"(r[0]), "=r"(r[1]), "=r"(r[2]), "=r"(r[3]) : "r"(addr));
}
__device__ __forceinline__ void mma16816(float* d, const uint32_t* a, const uint32_t* b) {
    asm volatile(
        "mma.sync.aligned.m16n8k16.row.col.f32.f16.f16.f32 "
        "{%0,%1,%2,%3}, {%4,%5,%6,%7}, {%8,%9}, {%0,%1,%2,%3};"
        : "+f"(d[0]), "+f"(d[1]), "+f"(d[2]), "+f"(d[3])
        : "r"(a[0]), "r"(a[1]), "r"(a[2]), "r"(a[3]), "r"(b[0]), "r"(b[1]));
}

// ---------------------------------------------------------------------------
// Kernel 1 (merged prologue): transpose + weight fusion
// ---------------------------------------------------------------------------
__global__ __launch_bounds__(256)
void prologue_kernel(const float* __restrict__ x,
                     const float* __restrict__ W,
                     const float* __restrict__ lA,
                     const float* __restrict__ lB) {
    const int tid = threadIdx.x;
    if (blockIdx.x < 1024) {
        __shared__ float sT[128][65];
        const int n = blockIdx.x >> 6;
        const int h = blockIdx.x & 63;
        const float* xp = x + ((size_t)n * C_IN * HWD + h) * HWD;
#pragma unroll
        for (int i = 0; i < 32; ++i) {
            int idx = i * 256 + tid;
            int c = idx >> 6, w = idx & 63;
            sT[c][w] = xp[(size_t)c * (HWD * HWD) + w];
        }
        __syncthreads();
        __half* dst = g_xh + ((size_t)(n * 64 + h) * 64) * C_IN;
#pragma unroll
        for (int i = 0; i < 16; ++i) {
            int idx = i * 256 + tid;
            int w = idx >> 6, c = (idx & 63) * 2;
            __half2 v = __floats2half2_rn(sT[c][w], sT[c + 1][w]);
            *(__half2*)(dst + (size_t)w * C_IN + c) = v;
        }
    } else {
        int idx = (blockIdx.x - 1024) * 256 + tid;   // oc*1152 + c*9 + tap
        int oc  = idx / KDIM;
        int rem = idx - oc * KDIM;
        int c   = rem / 9;
        int tap = rem - c * 9;
        float s = 0.f;
#pragma unroll
        for (int r = 0; r < 8; ++r)
            s += lB[oc * 8 + r] * lA[r * KDIM + rem];
        g_Bt[(size_t)oc * KDIM + tap * 128 + c] = __float2half_rn(W[idx] + 2.0f * s);
    }
}

// ---------------------------------------------------------------------------
// Kernel 2: implicit-conv GEMM, register-pipelined fragments.
// ---------------------------------------------------------------------------
__device__ __forceinline__ void load_stage(uint32_t sm, int it, int m0, int oc0, int tid) {
    const int s   = it & 3;
    const int tap = it >> 2;
    const int c0  = (it & 3) * 32;
    const int kh  = tap / 3;
    const int kw  = tap - kh * 3;
    const int n   = m0 >> 12;
    const int h0  = (m0 >> 6) & 63;

#pragma unroll
    for (int i = 0; i < 2; ++i) {
        int idx = tid + i * 256;
        int r   = idx >> 2;
        int q   = idx & 3;
        int hh  = h0 + (r >> 6) + kh - 1;
        int ww  = (r & 63) + kw - 1;
        bool ok = ((unsigned)hh < 64u) && ((unsigned)ww < 64u);
        const __half* src = ok
            ? &g_xh[(size_t)(((n * 64 + hh) * 64) + ww) * C_IN + c0 + q * 8]
            : &g_xh[0];
        cpasync16z(sm + s * A_ST + r * 80 + q * 16, src, ok ? 16u : 0u);
    }
#pragma unroll
    for (int i = 0; i < 2; ++i) {
        int idx = tid + i * 256;
        int r   = idx >> 2;
        int q   = idx & 3;
        cpasync16(sm + B_OFF + s * B_ST + r * 80 + q * 16,
                  &g_Bt[(size_t)(oc0 + r) * KDIM + tap * 128 + c0 + q * 8]);
    }
    cp_commit();
}

__global__ __launch_bounds__(256, 2)
void gemm_kernel(const float* __restrict__ bias, float* __restrict__ out) {
    extern __shared__ __align__(16) char smem[];
    const uint32_t sm = smem_u32(smem);

    const int tid  = threadIdx.x;
    const int wid  = tid >> 5;
    const int lane = tid & 31;
    const int oc0  = blockIdx.x * 128;
    const int m0   = blockIdx.y * 128;

    const int wm  = wid & 1;
    const int wn  = wid >> 1;
    const int grp = lane >> 3;
    const int l7  = lane & 7;

    // hoisted per-thread ldsm addresses (stage 0, ks 0)
    uint32_t aOff[4], bOff[2];
#pragma unroll
    for (int i = 0; i < 4; ++i)
        aOff[i] = sm + (uint32_t)(wm * 64 + i * 16 + (lane & 15)) * 80
                     + (uint32_t)(lane >> 4) * 16;
#pragma unroll
    for (int h = 0; h < 2; ++h)
        bOff[h] = sm + B_OFF + (uint32_t)(wn * 32 + h * 16 + (grp >> 1) * 8 + l7) * 80
                     + (uint32_t)(grp & 1) * 16;

    float acc[4][4][4];
#pragma unroll
    for (int i = 0; i < 4; ++i)
#pragma unroll
        for (int j = 0; j < 4; ++j)
#pragma unroll
            for (int p = 0; p < 4; ++p) acc[i][j][p] = 0.f;

    load_stage(sm, 0, m0, oc0, tid);
    load_stage(sm, 1, m0, oc0, tid);
    load_stage(sm, 2, m0, oc0, tid);
    cp_wait1();                        // stages 0,1 resident
    __syncthreads();

    uint32_t aR[4], aN[4], bR[4][2], bN[4][2];
    // prime: B(it0,ks0), A(it0,ks0,i0)
    {
        uint32_t r[4];
        ldsm4(r, bOff[0]); bR[0][0]=r[0]; bR[0][1]=r[1]; bR[1][0]=r[2]; bR[1][1]=r[3];
        ldsm4(r, bOff[1]); bR[2][0]=r[0]; bR[2][1]=r[1]; bR[3][0]=r[2]; bR[3][1]=r[3];
        ldsm4(aR, aOff[0]);
    }

    for (int it = 0; it < KITER; ++it) {
        const uint32_t sb  = (uint32_t)(it & 3) * (uint32_t)A_ST;
        const uint32_t sbN = (uint32_t)((it + 1) & 3) * (uint32_t)A_ST;
        if (it + 3 < KITER) load_stage(sm, it + 3, m0, oc0, tid);

        // ---- ks = 0 ----
        ldsm4(aN, aOff[1] + sb);
#pragma unroll
        for (int j = 0; j < 4; ++j) mma16816(acc[0][j], aR, bR[j]);
        ldsm4(aR, aOff[2] + sb);
#pragma unroll
        for (int j = 0; j < 4; ++j) mma16816(acc[1][j], aN, bR[j]);
        ldsm4(aN, aOff[3] + sb);
#pragma unroll
        for (int j = 0; j < 4; ++j) mma16816(acc[2][j], aR, bR[j]);
        {   // prefetch ks=1 frags
            uint32_t r[4];
            ldsm4(r, bOff[0] + sb + 32); bN[0][0]=r[0]; bN[0][1]=r[1]; bN[1][0]=r[2]; bN[1][1]=r[3];
            ldsm4(r, bOff[1] + sb + 32); bN[2][0]=r[0]; bN[2][1]=r[1]; bN[3][0]=r[2]; bN[3][1]=r[3];
            ldsm4(aR, aOff[0] + sb + 32);
        }
#pragma unroll
        for (int j = 0; j < 4; ++j) mma16816(acc[3][j], aN, bR[j]);

        // ---- ks = 1 ----
        ldsm4(aN, aOff[1] + sb + 32);
#pragma unroll
        for (int j = 0; j < 4; ++j) mma16816(acc[0][j], aR, bN[j]);
        ldsm4(aR, aOff[2] + sb + 32);
#pragma unroll
        for (int j = 0; j < 4; ++j) mma16816(acc[1][j], aN, bN[j]);
        ldsm4(aN, aOff[3] + sb + 32);
#pragma unroll
        for (int j = 0; j < 4; ++j) mma16816(acc[2][j], aR, bN[j]);

        if (it + 1 < KITER) {
            if (it < KITER - 3) cp_wait1(); else cp_wait0();
            // prefetch next-iteration ks0 frags (stage it+1, guaranteed resident)
            uint32_t r[4];
            ldsm4(r, bOff[0] + sbN); bR[0][0]=r[0]; bR[0][1]=r[1]; bR[1][0]=r[2]; bR[1][1]=r[3];
            ldsm4(r, bOff[1] + sbN); bR[2][0]=r[0]; bR[2][1]=r[1]; bR[3][0]=r[2]; bR[3][1]=r[3];
            ldsm4(aR, aOff[0] + sbN);
#pragma unroll
            for (int j = 0; j < 4; ++j) mma16816(acc[3][j], aN, bN[j]);
            __syncthreads();           // all reads of stage it complete
        } else {
#pragma unroll
            for (int j = 0; j < 4; ++j) mma16816(acc[3][j], aN, bN[j]);
        }
    }

    // epilogue
    const int g  = lane >> 2;
    const int c2 = (lane & 3) * 2;
    const int n  = m0 >> 12;
    float bia[4][2];
#pragma unroll
    for (int j = 0; j < 4; ++j) {
        int oc = oc0 + wn * 32 + j * 8 + c2;
        bia[j][0] = __ldg(bias + oc);
        bia[j][1] = __ldg(bias + oc + 1);
    }
#pragma unroll
    for (int i = 0; i < 4; ++i) {
#pragma unroll
        for (int rr = 0; rr < 2; ++rr) {
            int m = m0 + wm * 64 + i * 16 + g + rr * 8;
            size_t base = (size_t)n * (C_OUT * 4096) + (m & 4095);
#pragma unroll
            for (int j = 0; j < 4; ++j) {
                int oc = oc0 + wn * 32 + j * 8 + c2;
                out[base + (size_t)oc * 4096]       = acc[i][j][rr * 2 + 0] + bia[j][0];
                out[base + (size_t)(oc + 1) * 4096] = acc[i][j][rr * 2 + 1] + bia[j][1];
            }
        }
    }
}

// ---------------------------------------------------------------------------
extern "C" void kernel_launch(void* const* d_in, const int* in_sizes, int n_in,
                              void* d_out, int out_size) {
    const float* x      = (const float*)d_in[0];
    const float* W      = (const float*)d_in[1];
    const float* b      = (const float*)d_in[2];
    const float* lora_A = (const float*)d_in[3];
    const float* lora_B = (const float*)d_in[4];
    float* out = (float*)d_out;

    static int smem_set = 0;
    if (!smem_set) {
        cudaFuncSetAttribute(gemm_kernel,
                             cudaFuncAttributeMaxDynamicSharedMemorySize, SMEM_TOTAL);
        smem_set = 1;
    }

    prologue_kernel<<<1024 + (C_OUT * KDIM) / 256, 256>>>(x, W, lora_A, lora_B);
    gemm_kernel<<<dim3(2, M_TOTAL / 128), 256, SMEM_TOTAL>>>(b, out);
}

// round 11
// speedup vs baseline: 8.1206x; 1.1926x over previous
#include <cuda_runtime.h>
#include <cuda_fp16.h>
#include <cstdint>
#include <cstddef>

#define C_IN    128
#define C_OUT   256
#define HWD     64
#define KDIM    1152                  // 9 taps * 128 ch, k = tap*128 + c
#define M_TOTAL 65536
#define KC      64                    // K per stage (half a tap)
#define KITER   (KDIM / KC)           // 18
#define STAGES  3

#define A_ST    (128 * 128)           // 16KB
#define STAGE_B (2 * A_ST)            // A + B = 32KB
#define SMEM_TOTAL (STAGES * STAGE_B) // 98304 -> 2 CTAs/SM

// ---------------- scratch ----------------
__device__ __half g_xh[(size_t)M_TOTAL * C_IN];   // x in NHWC fp16
__device__ __half g_Bt[(size_t)C_OUT * KDIM];     // fused weights [oc][tap*128+c]

// ---------------- helpers ----------------
__device__ __forceinline__ uint32_t smem_u32(const void* p) {
    uint32_t a;
    asm("{ .reg .u64 t; cvta.to.shared.u64 t, %1; cvt.u32.u64 %0, t; }" : "=r"(a) : "l"(p));
    return a;
}
__device__ __forceinline__ void cpasync16(uint32_t dst, const void* src) {
    asm volatile("cp.async.cg.shared.global [%0], [%1], 16;" :: "r"(dst), "l"(src) : "memory");
}
__device__ __forceinline__ void cpasync16z(uint32_t dst, const void* src, uint32_t src_sz) {
    asm volatile("cp.async.cg.shared.global [%0], [%1], 16, %2;"
                 :: "r"(dst), "l"(src), "r"(src_sz) : "memory");
}
__device__ __forceinline__ void cp_commit() { asm volatile("cp.async.commit_group;" ::: "memory"); }
__device__ __forceinline__ void cp_wait1()  { asm volatile("cp.async.wait_group 1;" ::: "memory"); }
__device__ __forceinline__ void cp_wait0()  { asm volatile("cp.async.wait_group 0;" ::: "memory"); }

__device__ __forceinline__ void ldsm4(uint32_t* r, uint32_t addr) {
    asm volatile("ldmatrix.sync.aligned.m8n8.x4.shared.b16 {%0,%1,%2,%3}, [%4];"
                 : "=r"(r[0]), "=r"(r[1]), "=r"(r[2]), "=r"(r[3]) : "r"(addr));
}
__device__ __forceinline__ void mma16816(float* d, const uint32_t* a, const uint32_t* b) {
    asm volatile(
        "mma.sync.aligned.m16n8k16.row.col.f32.f16.f16.f32 "
        "{%0,%1,%2,%3}, {%4,%5,%6,%7}, {%8,%9}, {%0,%1,%2,%3};"
        : "+f"(d[0]), "+f"(d[1]), "+f"(d[2]), "+f"(d[3])
        : "r"(a[0]), "r"(a[1]), "r"(a[2]), "r"(a[3]), "r"(b[0]), "r"(b[1]));
}

// ---------------------------------------------------------------------------
// Kernel 1 (merged prologue): transpose + weight fusion
// ---------------------------------------------------------------------------
__global__ __launch_bounds__(256)
void prologue_kernel(const float* __restrict__ x,
                     const float* __restrict__ W,
                     const float* __restrict__ lA,
                     const float* __restrict__ lB) {
    const int tid = threadIdx.x;
    if (blockIdx.x < 1024) {
        __shared__ float sT[128][65];
        const int n = blockIdx.x >> 6;
        const int h = blockIdx.x & 63;
        const float* xp = x + ((size_t)n * C_IN * HWD + h) * HWD;
#pragma unroll
        for (int i = 0; i < 32; ++i) {
            int idx = i * 256 + tid;
            int c = idx >> 6, w = idx & 63;
            sT[c][w] = xp[(size_t)c * (HWD * HWD) + w];
        }
        __syncthreads();
        __half* dst = g_xh + ((size_t)(n * 64 + h) * 64) * C_IN;
#pragma unroll
        for (int i = 0; i < 16; ++i) {
            int idx = i * 256 + tid;
            int w = idx >> 6, c = (idx & 63) * 2;
            __half2 v = __floats2half2_rn(sT[c][w], sT[c + 1][w]);
            *(__half2*)(dst + (size_t)w * C_IN + c) = v;
        }
    } else {
        int idx = (blockIdx.x - 1024) * 256 + tid;   // oc*1152 + c*9 + tap
        int oc  = idx / KDIM;
        int rem = idx - oc * KDIM;
        int c   = rem / 9;
        int tap = rem - c * 9;
        float s = 0.f;
#pragma unroll
        for (int r = 0; r < 8; ++r)
            s += lB[oc * 8 + r] * lA[r * KDIM + rem];
        g_Bt[(size_t)oc * KDIM + tap * 128 + c] = __float2half_rn(W[idx] + 2.0f * s);
    }
}

// ---------------------------------------------------------------------------
// Kernel 2: implicit-conv GEMM. CTA 128m x 128oc, KC=64, XOR-swizzled smem.
// smem chunk layout: row r (128B), chunk c at offset r*128 + (c ^ (r&7))*16.
// ---------------------------------------------------------------------------
__device__ __forceinline__ void load_stage(uint32_t sm, int it, int m0, int oc0, int tid) {
    const uint32_t st = (uint32_t)(it % STAGES) * STAGE_B;
    const int tap = it >> 1;
    const int c0  = (it & 1) * 64;
    const int kh  = tap / 3;
    const int kw  = tap - kh * 3;
    const int n   = m0 >> 12;
    const int h0  = (m0 >> 6) & 63;

    // A: 128 m-rows x 128B (64 ch); 1024 chunks / 256 thr = 4 each
#pragma unroll
    for (int i = 0; i < 4; ++i) {
        int idx = tid + i * 256;
        int r   = idx >> 3;
        int q   = idx & 7;
        int hh  = h0 + (r >> 6) + kh - 1;
        int ww  = (r & 63) + kw - 1;
        bool ok = ((unsigned)hh < 64u) && ((unsigned)ww < 64u);
        const __half* src = ok
            ? &g_xh[(size_t)(((n * 64 + hh) * 64) + ww) * C_IN + c0 + q * 8]
            : &g_xh[0];
        cpasync16z(sm + st + r * 128 + ((q ^ (r & 7)) * 16), src, ok ? 16u : 0u);
    }
    // B: 128 oc-rows x 128B
#pragma unroll
    for (int i = 0; i < 4; ++i) {
        int idx = tid + i * 256;
        int r   = idx >> 3;
        int q   = idx & 7;
        cpasync16(sm + st + A_ST + r * 128 + ((q ^ (r & 7)) * 16),
                  &g_Bt[(size_t)(oc0 + r) * KDIM + tap * 128 + c0 + q * 8]);
    }
    cp_commit();
}

__global__ __launch_bounds__(256, 2)
void gemm_kernel(const float* __restrict__ bias, float* __restrict__ out) {
    extern __shared__ __align__(16) char smem[];
    const uint32_t sm = smem_u32(smem);

    const int tid  = threadIdx.x;
    const int wid  = tid >> 5;
    const int lane = tid & 31;
    const int oc0  = blockIdx.x * 128;
    const int m0   = blockIdx.y * 128;

    const int wm  = wid & 1;
    const int wn  = wid >> 1;
    const int grp = lane >> 3;
    const int l7  = lane & 7;
    const int hi  = lane >> 4;

    // hoisted row bases + per-ksub swizzled chunk offsets
    uint32_t aAddr[4], bAddr[2], cA[4], cB[4];
#pragma unroll
    for (int i = 0; i < 4; ++i)
        aAddr[i] = sm + (uint32_t)(wm * 64 + i * 16 + (lane & 15)) * 128;
#pragma unroll
    for (int h = 0; h < 2; ++h)
        bAddr[h] = sm + A_ST + (uint32_t)(wn * 32 + h * 16 + (grp >> 1) * 8 + l7) * 128;
#pragma unroll
    for (int ks = 0; ks < 4; ++ks) {
        cA[ks] = (uint32_t)(((ks * 2 + hi) ^ l7) * 16);
        cB[ks] = (uint32_t)(((ks * 2 + (grp & 1)) ^ l7) * 16);
    }

    float acc[4][4][4];
#pragma unroll
    for (int i = 0; i < 4; ++i)
#pragma unroll
        for (int j = 0; j < 4; ++j)
#pragma unroll
            for (int p = 0; p < 4; ++p) acc[i][j][p] = 0.f;

    load_stage(sm, 0, m0, oc0, tid);
    load_stage(sm, 1, m0, oc0, tid);
    cp_wait1();                       // stage 0 resident
    __syncthreads();

    uint32_t aR[4], aN[4], bF[2][4][2];
    {   // prime: B(it0, ks0), A(it0, ks0, i0)
        uint32_t r[4];
        ldsm4(r, bAddr[0] + cB[0]); bF[0][0][0]=r[0]; bF[0][0][1]=r[1]; bF[0][1][0]=r[2]; bF[0][1][1]=r[3];
        ldsm4(r, bAddr[1] + cB[0]); bF[0][2][0]=r[0]; bF[0][2][1]=r[1]; bF[0][3][0]=r[2]; bF[0][3][1]=r[3];
        ldsm4(aR, aAddr[0] + cA[0]);
    }

    for (int it = 0; it < KITER; ++it) {
        const uint32_t sb  = (uint32_t)(it % STAGES) * STAGE_B;
        const uint32_t sbN = (uint32_t)((it + 1) % STAGES) * STAGE_B;
        if (it + 2 < KITER) load_stage(sm, it + 2, m0, oc0, tid);

#pragma unroll
        for (int ks = 0; ks < 4; ++ks) {
            const int cur = ks & 1;
            const int nxt = cur ^ 1;
            uint32_t (*bR)[2] = bF[cur];

            ldsm4(aN, aAddr[1] + sb + cA[ks]);
#pragma unroll
            for (int j = 0; j < 4; ++j) mma16816(acc[0][j], aR, bR[j]);
            ldsm4(aR, aAddr[2] + sb + cA[ks]);
#pragma unroll
            for (int j = 0; j < 4; ++j) mma16816(acc[1][j], aN, bR[j]);
            ldsm4(aN, aAddr[3] + sb + cA[ks]);
#pragma unroll
            for (int j = 0; j < 4; ++j) mma16816(acc[2][j], aR, bR[j]);

            if (ks < 3) {              // prefetch next ksub
                uint32_t r[4];
                ldsm4(r, bAddr[0] + sb + cB[ks + 1]);
                bF[nxt][0][0]=r[0]; bF[nxt][0][1]=r[1]; bF[nxt][1][0]=r[2]; bF[nxt][1][1]=r[3];
                ldsm4(r, bAddr[1] + sb + cB[ks + 1]);
                bF[nxt][2][0]=r[0]; bF[nxt][2][1]=r[1]; bF[nxt][3][0]=r[2]; bF[nxt][3][1]=r[3];
                ldsm4(aR, aAddr[0] + sb + cA[ks + 1]);
#pragma unroll
                for (int j = 0; j < 4; ++j) mma16816(acc[3][j], aN, bR[j]);
            } else if (it + 1 < KITER) {
                if (it < KITER - 3) cp_wait1(); else cp_wait0();
                uint32_t r[4];     // prefetch next-iteration ks0 (stage it+1 resident)
                ldsm4(r, bAddr[0] + sbN + cB[0]);
                bF[nxt][0][0]=r[0]; bF[nxt][0][1]=r[1]; bF[nxt][1][0]=r[2]; bF[nxt][1][1]=r[3];
                ldsm4(r, bAddr[1] + sbN + cB[0]);
                bF[nxt][2][0]=r[0]; bF[nxt][2][1]=r[1]; bF[nxt][3][0]=r[2]; bF[nxt][3][1]=r[3];
                ldsm4(aR, aAddr[0] + sbN + cA[0]);
#pragma unroll
                for (int j = 0; j < 4; ++j) mma16816(acc[3][j], aN, bR[j]);
                __syncthreads();   // all reads of stage it done -> reusable
            } else {
#pragma unroll
                for (int j = 0; j < 4; ++j) mma16816(acc[3][j], aN, bR[j]);
            }
        }
    }

    // epilogue
    const int g  = lane >> 2;
    const int c2 = (lane & 3) * 2;
    const int n  = m0 >> 12;
    float bia[4][2];
#pragma unroll
    for (int j = 0; j < 4; ++j) {
        int oc = oc0 + wn * 32 + j * 8 + c2;
        bia[j][0] = __ldg(bias + oc);
        bia[j][1] = __ldg(bias + oc + 1);
    }
#pragma unroll
    for (int i = 0; i < 4; ++i) {
#pragma unroll
        for (int rr = 0; rr < 2; ++rr) {
            int m = m0 + wm * 64 + i * 16 + g + rr * 8;
            size_t base = (size_t)n * (C_OUT * 4096) + (m & 4095);
#pragma unroll
            for (int j = 0; j < 4; ++j) {
                int oc = oc0 + wn * 32 + j * 8 + c2;
                out[base + (size_t)oc * 4096]       = acc[i][j][rr * 2 + 0] + bia[j][0];
                out[base + (size_t)(oc + 1) * 4096] = acc[i][j][rr * 2 + 1] + bia[j][1];
            }
        }
    }
}

// ---------------------------------------------------------------------------
extern "C" void kernel_launch(void* const* d_in, const int* in_sizes, int n_in,
                              void* d_out, int out_size) {
    const float* x      = (const float*)d_in[0];
    const float* W      = (const float*)d_in[1];
    const float* b      = (const float*)d_in[2];
    const float* lora_A = (const float*)d_in[3];
    const float* lora_B = (const float*)d_in[4];
    float* out = (float*)d_out;

    static int smem_set = 0;
    if (!smem_set) {
        cudaFuncSetAttribute(gemm_kernel,
                             cudaFuncAttributeMaxDynamicSharedMemorySize, SMEM_TOTAL);
        smem_set = 1;
    }

    prologue_kernel<<<1024 + (C_OUT * KDIM) / 256, 256>>>(x, W, lora_A, lora_B);
    gemm_kernel<<<dim3(2, M_TOTAL / 128), 256, SMEM_TOTAL>>>(b, out);
}